// round 3
// baseline (speedup 1.0000x reference)
#include <cuda_runtime.h>
#include <cuda_bf16.h>

#define BB 32
#define SS 2048
#define HH 1024

#define MT 128
#define NT 128
#define KT 32
#define PAD 4

typedef unsigned long long ull;

// Scratch (device globals: no allocations allowed)
__device__ float g_pre[BB * HH];     // q_proj + Wa_b + Ua_b  (per batch, per channel)
__device__ float g_scores[BB * SS];  // pre-softmax scores

// ---------- packed f32x2 helpers ----------
__device__ __forceinline__ ull pack_dup(float x) {
    ull r;
    asm("mov.b64 %0, {%1, %1};" : "=l"(r) : "f"(x));
    return r;
}
__device__ __forceinline__ void ffma2(ull& c, ull a, ull b) {
    asm("fma.rn.f32x2 %0, %1, %2, %0;" : "+l"(c) : "l"(a), "l"(b));
}

// ---------------------------------------------------------------------------
// K1: pre[b,k] = sum_h query[b,h]*Wa_w[k,h] + Wa_b[k] + Ua_b[k]
// One warp per output element; coalesced Wa_w reads.
// grid = B*H/8 blocks of 256 threads (8 warps).
// ---------------------------------------------------------------------------
__global__ void qproj_kernel(const float* __restrict__ query,
                             const float* __restrict__ Wa_w,
                             const float* __restrict__ Wa_b,
                             const float* __restrict__ Ua_b) {
    int gw = blockIdx.x * 8 + (threadIdx.x >> 5);
    int lane = threadIdx.x & 31;
    int b = gw >> 10;        // / HH
    int k = gw & (HH - 1);
    const float* q = query + b * HH;
    const float* w = Wa_w + (size_t)k * HH;
    float sum = 0.f;
#pragma unroll 8
    for (int h = lane; h < HH; h += 32) sum += q[h] * w[h];
#pragma unroll
    for (int off = 16; off; off >>= 1) sum += __shfl_xor_sync(0xffffffffu, sum, off);
    if (lane == 0) g_pre[b * HH + k] = sum + Wa_b[k] + Ua_b[k];
}

// ---------------------------------------------------------------------------
// K2: fused  scores[b,s] = sum_n tanh( keys[b,s,:]·Ua_w[n,:] + pre[b,n] ) * Va[n]
// Register-tiled fp32 GEMM (128x128 tile, 256 threads, 8x8 per thread) with
// packed f32x2 FMAs; tanh+Va reduction fused in the per-n-tile epilogue so the
// [B,S,H] intermediate never touches memory.
// grid = (S/MT, B), block = 256 (16x16).
// ---------------------------------------------------------------------------
__global__ __launch_bounds__(256) void scores_kernel(
    const float* __restrict__ keys,
    const float* __restrict__ Ua_w,
    const float* __restrict__ Va_w) {
    __shared__ __align__(16) float As[KT][MT + PAD];  // keys tile, transposed [k][m]
    __shared__ __align__(16) float Bs[KT][NT + PAD];  // Ua tile,   transposed [k][n]

    const int b = blockIdx.y;
    const int s0 = blockIdx.x * MT;
    const int tid = threadIdx.x;
    const int tx = tid & 15;   // column group (n)
    const int ty = tid >> 4;   // row group (s)
    const float* Abase = keys + ((size_t)b * SS + s0) * HH;

    float srow[8];
#pragma unroll
    for (int i = 0; i < 8; i++) srow[i] = 0.f;

    for (int n0 = 0; n0 < HH; n0 += NT) {
        ull cc[8][4];
#pragma unroll
        for (int i = 0; i < 8; i++)
#pragma unroll
            for (int jj = 0; jj < 4; jj++) cc[i][jj] = 0ull;

        for (int k0 = 0; k0 < HH; k0 += KT) {
            // Stage tiles: 128 rows x 32 k each, float4 global loads,
            // transposed scatter into smem.
#pragma unroll
            for (int r = 0; r < 4; r++) {
                int idx = tid + 256 * r;
                int m = idx >> 3;
                int kq = (idx & 7) << 2;
                float4 av = *reinterpret_cast<const float4*>(Abase + (size_t)m * HH + k0 + kq);
                As[kq + 0][m] = av.x; As[kq + 1][m] = av.y;
                As[kq + 2][m] = av.z; As[kq + 3][m] = av.w;
                float4 bv = *reinterpret_cast<const float4*>(Ua_w + (size_t)(n0 + m) * HH + k0 + kq);
                Bs[kq + 0][m] = bv.x; Bs[kq + 1][m] = bv.y;
                Bs[kq + 2][m] = bv.z; Bs[kq + 3][m] = bv.w;
            }
            __syncthreads();

#pragma unroll 8
            for (int k = 0; k < KT; k++) {
                // b-pairs read directly as packed f32x2 (consecutive n)
                ulonglong2 bl0 = *reinterpret_cast<const ulonglong2*>(&Bs[k][tx * 8]);
                ulonglong2 bl1 = *reinterpret_cast<const ulonglong2*>(&Bs[k][tx * 8 + 4]);
                ull bb0 = bl0.x, bb1 = bl0.y, bb2 = bl1.x, bb3 = bl1.y;
                float4 a0 = *reinterpret_cast<const float4*>(&As[k][ty * 8]);
                float4 a1 = *reinterpret_cast<const float4*>(&As[k][ty * 8 + 4]);
                float av[8] = {a0.x, a0.y, a0.z, a0.w, a1.x, a1.y, a1.z, a1.w};
#pragma unroll
                for (int i = 0; i < 8; i++) {
                    ull ad = pack_dup(av[i]);
                    ffma2(cc[i][0], ad, bb0);
                    ffma2(cc[i][1], ad, bb1);
                    ffma2(cc[i][2], ad, bb2);
                    ffma2(cc[i][3], ad, bb3);
                }
            }
            __syncthreads();
        }

        // Epilogue for this n-tile: tanh + dot with Va, accumulate per-row score
#pragma unroll
        for (int jj = 0; jj < 4; jj++) {
            int n = n0 + tx * 8 + jj * 2;
            float p0 = g_pre[b * HH + n];
            float p1 = g_pre[b * HH + n + 1];
            float v0 = Va_w[n];
            float v1 = Va_w[n + 1];
#pragma unroll
            for (int i = 0; i < 8; i++) {
                union { ull u; float2 f; } cv;
                cv.u = cc[i][jj];
                srow[i] += tanhf(cv.f.x + p0) * v0 + tanhf(cv.f.y + p1) * v1;
            }
        }
    }

    // Reduce over the 16 column-group threads (tx = lane&15, so xor 1/2/4/8
    // stays within the half-warp that shares these rows).
#pragma unroll
    for (int i = 0; i < 8; i++) {
        float v = srow[i];
        v += __shfl_xor_sync(0xffffffffu, v, 1);
        v += __shfl_xor_sync(0xffffffffu, v, 2);
        v += __shfl_xor_sync(0xffffffffu, v, 4);
        v += __shfl_xor_sync(0xffffffffu, v, 8);
        if (tx == 0) g_scores[b * SS + s0 + ty * 8 + i] = v;
    }
}

// ---------------------------------------------------------------------------
// K3: softmax over S per batch. Note: Va_b dropped (softmax shift-invariant).
// grid = B, block = 256 (8 elements/thread).
// ---------------------------------------------------------------------------
__global__ void softmax_kernel(float* __restrict__ out_w) {
    int b = blockIdx.x;
    int tid = threadIdx.x;
    __shared__ float red[256];
    float v[8];
    float mx = -1e30f;
#pragma unroll
    for (int j = 0; j < 8; j++) {
        v[j] = g_scores[b * SS + tid + 256 * j];
        mx = fmaxf(mx, v[j]);
    }
    red[tid] = mx;
    __syncthreads();
    for (int off = 128; off; off >>= 1) {
        if (tid < off) red[tid] = fmaxf(red[tid], red[tid + off]);
        __syncthreads();
    }
    mx = red[0];
    __syncthreads();
    float sum = 0.f;
#pragma unroll
    for (int j = 0; j < 8; j++) {
        v[j] = __expf(v[j] - mx);
        sum += v[j];
    }
    red[tid] = sum;
    __syncthreads();
    for (int off = 128; off; off >>= 1) {
        if (tid < off) red[tid] += red[tid + off];
        __syncthreads();
    }
    float inv = 1.f / red[0];
#pragma unroll
    for (int j = 0; j < 8; j++) out_w[b * SS + tid + 256 * j] = v[j] * inv;
}

// ---------------------------------------------------------------------------
// K4: context[b,h] = sum_s weights[b,s] * keys[b,s,h]   (memory-bound)
// grid = (B, H/256), block = 256; weights staged in smem, coalesced keys.
// ---------------------------------------------------------------------------
__global__ void context_kernel(const float* __restrict__ keys,
                               const float* __restrict__ w,
                               float* __restrict__ ctx) {
    int b = blockIdx.x;
    int h = blockIdx.y * 256 + threadIdx.x;
    __shared__ float ws[256];
    float acc = 0.f;
    const float* kb = keys + (size_t)b * SS * HH;
    for (int st = 0; st < SS; st += 256) {
        ws[threadIdx.x] = w[b * SS + st + threadIdx.x];
        __syncthreads();
#pragma unroll 8
        for (int ssv = 0; ssv < 256; ssv++)
            acc += ws[ssv] * kb[(size_t)(st + ssv) * HH + h];
        __syncthreads();
    }
    ctx[b * HH + h] = acc;
}

// ---------------------------------------------------------------------------
extern "C" void kernel_launch(void* const* d_in, const int* in_sizes, int n_in,
                              void* d_out, int out_size) {
    const float* query = (const float*)d_in[0];  // [B,1,H]
    const float* keys  = (const float*)d_in[1];  // [B,S,H]
    const float* Wa_w  = (const float*)d_in[2];  // [H,H]
    const float* Wa_b  = (const float*)d_in[3];  // [H]
    const float* Ua_w  = (const float*)d_in[4];  // [H,H]
    const float* Ua_b  = (const float*)d_in[5];  // [H]
    const float* Va_w  = (const float*)d_in[6];  // [1,H]
    // d_in[7] = Va_b: softmax-shift-invariant, unused.

    float* out = (float*)d_out;
    float* out_ctx = out;            // context [B,1,H] -> B*H floats
    float* out_w = out + BB * HH;    // weights [B,1,S] -> B*S floats

    qproj_kernel<<<BB * HH / 8, 256>>>(query, Wa_w, Wa_b, Ua_b);
    dim3 g2(SS / MT, BB);
    scores_kernel<<<g2, 256>>>(keys, Ua_w, Va_w);
    softmax_kernel<<<BB, 256>>>(out_w);
    context_kernel<<<dim3(BB, HH / 256), 256>>>(keys, out_w, out_ctx);
}

// round 5
// speedup vs baseline: 4.2831x; 4.2831x over previous
#include <cuda_runtime.h>
#include <cuda_bf16.h>
#include <cstdint>

#define BB 32
#define SS 2048
#define HH 1024

// scores kernel geometry
#define MT 128            // CTA M (keys rows)
#define NTILE 128         // CTA N per pass
#define NPASS (HH / NTILE)
#define KC 32             // K floats per chunk (128B per row)
#define NCHUNK (HH / KC)  // 32
#define NSTG 3

#define STG_BYTES 32768           // 16KB A + 16KB B
#define A_OFF(s)  ((s) * STG_BYTES)
#define B_OFF(s)  ((s) * STG_BYTES + 16384)
#define PRE_OFF   (NSTG * STG_BYTES)        // 98304
#define VA_OFF    (PRE_OFF + 4096)          // 102400
#define RED_OFF   (VA_OFF + 4096)           // 106496
#define SMEM_BYTES (RED_OFF + 1024)         // 107520

// ---------- device scratch ----------
__device__ float g_pre[BB * HH];
__device__ float g_scores[BB * SS];
__device__ float g_part[16 * BB * HH];

// ---------- helpers ----------
__device__ __forceinline__ void cp16(void* dst_smem, const void* src) {
    uint32_t d;
    asm("{ .reg .u64 t; cvta.to.shared.u64 t, %1; cvt.u32.u64 %0, t; }" : "=r"(d) : "l"(dst_smem));
    asm volatile("cp.async.cg.shared.global [%0], [%1], 16;" :: "r"(d), "l"(src) : "memory");
}
#define CP_COMMIT() asm volatile("cp.async.commit_group;" ::: "memory")
template <int N> __device__ __forceinline__ void cp_wait() {
    asm volatile("cp.async.wait_group %0;" :: "n"(N) : "memory");
}

#define MMA_TF32(c, a, b0, b1) \
    asm volatile("mma.sync.aligned.m16n8k8.row.col.f32.tf32.tf32.f32 " \
        "{%0,%1,%2,%3}, {%4,%5,%6,%7}, {%8,%9}, {%0,%1,%2,%3};" \
        : "+f"((c)[0]), "+f"((c)[1]), "+f"((c)[2]), "+f"((c)[3]) \
        : "r"((a)[0]), "r"((a)[1]), "r"((a)[2]), "r"((a)[3]), "r"(b0), "r"(b1))

__device__ __forceinline__ float ftanh(float x) {
    // tanh(x) = 1 - 2/(exp(2x)+1) ; saturates correctly at +/-1
    float e = __expf(2.0f * x);
    return 1.0f - __fdividef(2.0f, e + 1.0f);
}

// ---------------------------------------------------------------------------
// K1: pre[b,k] = query[b]·Wa_w[k] + Wa_b[k] + Ua_b[k]
// ---------------------------------------------------------------------------
__global__ void qproj_kernel(const float* __restrict__ query,
                             const float* __restrict__ Wa_w,
                             const float* __restrict__ Wa_b,
                             const float* __restrict__ Ua_b) {
    int gw = blockIdx.x * 8 + (threadIdx.x >> 5);
    int lane = threadIdx.x & 31;
    int b = gw >> 10;
    int k = gw & (HH - 1);
    const float* q = query + b * HH;
    const float* w = Wa_w + (size_t)k * HH;
    float sum = 0.f;
#pragma unroll 8
    for (int h = lane; h < HH; h += 32) sum += q[h] * w[h];
#pragma unroll
    for (int off = 16; off; off >>= 1) sum += __shfl_xor_sync(0xffffffffu, sum, off);
    if (lane == 0) g_pre[b * HH + k] = sum + Wa_b[k] + Ua_b[k];
}

// ---------------------------------------------------------------------------
// K2: fused scores via mma.sync tf32 (sm_80-class PTX; works on plain sm_103).
// grid = (S/128, B), block = 256 (8 warps: 4 in M x 2 in N).
// ---------------------------------------------------------------------------
__global__ __launch_bounds__(256, 2) void scores_kernel(
    const float* __restrict__ keys,
    const float* __restrict__ Ua_w,
    const float* __restrict__ Va_w) {
    extern __shared__ char smem[];
    float* pre_s = (float*)(smem + PRE_OFF);
    float* va_s  = (float*)(smem + VA_OFF);
    float* red   = (float*)(smem + RED_OFF);   // [2][128]

    const int tid = threadIdx.x;
    const int wid = tid >> 5;
    const int lane = tid & 31;
    const int g = lane >> 2;       // group 0..7
    const int tg = lane & 3;       // thread-in-group
    const int wm = wid & 3;        // warp M index 0..3
    const int wn = wid >> 2;       // warp N index 0..1
    const int b = blockIdx.y;
    const int s0 = blockIdx.x * MT;

    const char* gA = (const char*)(keys + ((size_t)b * SS + s0) * HH);

    // preload pre + Va
#pragma unroll
    for (int i = tid; i < HH; i += 256) {
        pre_s[i] = g_pre[b * HH + i];
        va_s[i]  = Va_w[i];
    }

    float sacc[2][2] = {{0.f, 0.f}, {0.f, 0.f}};   // [mi][half] row partials

    // staging task decomposition: id = tid + 256*r -> row = id>>3, seg = id&7
    const int l_row = tid >> 1;               // not used; per-r mapping below

    for (int nt = 0; nt < NPASS; nt++) {
        const char* gB = (const char*)(Ua_w + (size_t)nt * NTILE * HH);

        float acc[2][8][4];
#pragma unroll
        for (int mi = 0; mi < 2; mi++)
#pragma unroll
            for (int ni = 0; ni < 8; ni++)
#pragma unroll
                for (int q = 0; q < 4; q++) acc[mi][ni][q] = 0.f;

        // chunk loader: stage st <- k-chunk c (both A and B tiles)
        auto load_chunk = [&](int st, int c) {
            char* Ab = smem + A_OFF(st);
            char* Bb = smem + B_OFF(st);
            size_t kbyte = (size_t)c * 128;
#pragma unroll
            for (int r = 0; r < 4; r++) {
                int id = tid + 256 * r;
                int m = id >> 3;
                int j = id & 7;
                uint32_t sw = (uint32_t)(j * 16) ^ ((uint32_t)(m & 7) << 4);
                cp16(Ab + m * 128 + sw, gA + (size_t)m * HH * 4 + kbyte + j * 16);
                cp16(Bb + m * 128 + sw, gB + (size_t)m * HH * 4 + kbyte + j * 16);
            }
        };

        // prologue: 2 chunks in flight
        load_chunk(0, 0); CP_COMMIT();
        load_chunk(1, 1); CP_COMMIT();

        for (int c = 0; c < NCHUNK; c++) {
            cp_wait<1>();          // chunk c complete (c+1 may be pending)
            __syncthreads();       // all warps done with chunk c-1's stage
            if (c + 2 < NCHUNK) load_chunk((c + 2) % NSTG, c + 2);
            CP_COMMIT();           // keep group accounting uniform

            const char* Ab = smem + A_OFF(c % NSTG);
            const char* Bb = smem + B_OFF(c % NSTG);
#pragma unroll
            for (int s = 0; s < 4; s++) {
                uint32_t sw  = ((uint32_t)((s * 8 + tg) * 4)) ^ ((uint32_t)g << 4);
                uint32_t sw4 = sw ^ 16u;
                uint32_t a[2][4];
#pragma unroll
                for (int mi = 0; mi < 2; mi++) {
                    const char* base = Ab + (wm * 32 + mi * 16 + g) * 128;
                    a[mi][0] = *(const uint32_t*)(base + sw);
                    a[mi][1] = *(const uint32_t*)(base + 8 * 128 + sw);
                    a[mi][2] = *(const uint32_t*)(base + sw4);
                    a[mi][3] = *(const uint32_t*)(base + 8 * 128 + sw4);
                }
#pragma unroll
                for (int ni = 0; ni < 8; ni++) {
                    const char* base = Bb + (wn * 64 + ni * 8 + g) * 128;
                    uint32_t b0 = *(const uint32_t*)(base + sw);
                    uint32_t b1 = *(const uint32_t*)(base + sw4);
                    MMA_TF32(acc[0][ni], a[0], b0, b1);
                    MMA_TF32(acc[1][ni], a[1], b0, b1);
                }
            }
        }

        // epilogue for this n-tile: tanh + Va reduce into row partials
#pragma unroll
        for (int mi = 0; mi < 2; mi++) {
#pragma unroll
            for (int ni = 0; ni < 8; ni++) {
                int col0 = nt * NTILE + wn * 64 + ni * 8 + tg * 2;
                float p0 = pre_s[col0], p1 = pre_s[col0 + 1];
                float v0 = va_s[col0],  v1 = va_s[col0 + 1];
                sacc[mi][0] += ftanh(acc[mi][ni][0] + p0) * v0
                             + ftanh(acc[mi][ni][1] + p1) * v1;
                sacc[mi][1] += ftanh(acc[mi][ni][2] + p0) * v0
                             + ftanh(acc[mi][ni][3] + p1) * v1;
            }
        }
        __syncthreads();   // protect stage reuse by next pass prologue
    }

    // reduce within quad (tg lanes), then across the two N-warps via smem
#pragma unroll
    for (int mi = 0; mi < 2; mi++)
#pragma unroll
        for (int h = 0; h < 2; h++) {
            float v = sacc[mi][h];
            v += __shfl_xor_sync(0xffffffffu, v, 1);
            v += __shfl_xor_sync(0xffffffffu, v, 2);
            if (tg == 0) red[wn * 128 + wm * 32 + mi * 16 + h * 8 + g] = v;
        }
    __syncthreads();
    if (tid < 128)
        g_scores[b * SS + s0 + tid] = red[tid] + red[128 + tid];
}

// ---------------------------------------------------------------------------
// K3: softmax over S per batch (Va_b dropped: shift-invariant).
// ---------------------------------------------------------------------------
__global__ void softmax_kernel(float* __restrict__ out_w) {
    int b = blockIdx.x;
    int tid = threadIdx.x;
    __shared__ float red[256];
    float v[8];
    float mx = -1e30f;
#pragma unroll
    for (int j = 0; j < 8; j++) {
        v[j] = g_scores[b * SS + tid + 256 * j];
        mx = fmaxf(mx, v[j]);
    }
    red[tid] = mx;
    __syncthreads();
    for (int off = 128; off; off >>= 1) {
        if (tid < off) red[tid] = fmaxf(red[tid], red[tid + off]);
        __syncthreads();
    }
    mx = red[0];
    __syncthreads();
    float sum = 0.f;
#pragma unroll
    for (int j = 0; j < 8; j++) {
        v[j] = __expf(v[j] - mx);
        sum += v[j];
    }
    red[tid] = sum;
    __syncthreads();
    for (int off = 128; off; off >>= 1) {
        if (tid < off) red[tid] += red[tid + off];
        __syncthreads();
    }
    float inv = 1.f / red[0];
#pragma unroll
    for (int j = 0; j < 8; j++) out_w[b * SS + tid + 256 * j] = v[j] * inv;
}

// ---------------------------------------------------------------------------
// K4a: context partials over 16 S-chunks of 128 (deterministic, no atomics)
// ---------------------------------------------------------------------------
__global__ void context_part_kernel(const float* __restrict__ keys,
                                    const float* __restrict__ w) {
    int b = blockIdx.x;
    int cy = blockIdx.y;
    int s0 = cy * 128;
    int t = threadIdx.x;
    __shared__ float ws[128];
    if (t < 128) ws[t] = w[b * SS + s0 + t];
    __syncthreads();
    const float4* kb = (const float4*)(keys + ((size_t)b * SS + s0) * HH);
    float4 acc = {0.f, 0.f, 0.f, 0.f};
    for (int s = 0; s < 128; s += 4) {
#pragma unroll
        for (int u = 0; u < 4; u++) {
            float wv = ws[s + u];
            float4 kv = kb[(size_t)(s + u) * (HH / 4) + t];
            acc.x += wv * kv.x; acc.y += wv * kv.y;
            acc.z += wv * kv.z; acc.w += wv * kv.w;
        }
    }
    *(float4*)&g_part[((size_t)cy * BB + b) * HH + t * 4] = acc;
}

__global__ void context_reduce_kernel(float* __restrict__ ctx) {
    int i = blockIdx.x * 256 + threadIdx.x;
    float s = 0.f;
#pragma unroll
    for (int j = 0; j < 16; j++) s += g_part[(size_t)j * BB * HH + i];
    ctx[i] = s;
}

// ---------------------------------------------------------------------------
extern "C" void kernel_launch(void* const* d_in, const int* in_sizes, int n_in,
                              void* d_out, int out_size) {
    const float* query = (const float*)d_in[0];
    const float* keys  = (const float*)d_in[1];
    const float* Wa_w  = (const float*)d_in[2];
    const float* Wa_b  = (const float*)d_in[3];
    const float* Ua_w  = (const float*)d_in[4];
    const float* Ua_b  = (const float*)d_in[5];
    const float* Va_w  = (const float*)d_in[6];
    // d_in[7] = Va_b: softmax shift-invariant, unused.

    float* out = (float*)d_out;
    float* out_ctx = out;            // [B,1,H]
    float* out_w = out + BB * HH;    // [B,1,S]

    cudaFuncSetAttribute(scores_kernel, cudaFuncAttributeMaxDynamicSharedMemorySize,
                         SMEM_BYTES);

    qproj_kernel<<<BB * HH / 8, 256>>>(query, Wa_w, Wa_b, Ua_b);
    scores_kernel<<<dim3(SS / MT, BB), 256, SMEM_BYTES>>>(keys, Ua_w, Va_w);
    softmax_kernel<<<BB, 256>>>(out_w);
    context_part_kernel<<<dim3(BB, 16), 256>>>(keys, out_w);
    context_reduce_kernel<<<BB * HH / 256, 256>>>(out_ctx);
}

// round 8
// speedup vs baseline: 4.3415x; 1.0136x over previous
#include <cuda_runtime.h>
#include <cuda_bf16.h>
#include <cstdint>

#define BB 32
#define SS 2048
#define HH 1024

// scores kernel geometry
#define MT 128            // CTA M (keys rows)
#define NTILE 256         // CTA N per pass (acc in regs: 128 f32/thread)
#define NPASS (HH / NTILE)   // 4
#define KC 32             // K floats per chunk (128B per row)
#define NCHUNKS (NPASS * (HH / KC))  // flat stream: 4*32 = 128
#define NSTG 4

#define STG_BYTES (16384 + 32768)   // A 16KB + B 32KB = 48KB
#define A_OFF(s)  ((s) * STG_BYTES)
#define B_OFF(s)  ((s) * STG_BYTES + 16384)
#define PRE_OFF   (NSTG * STG_BYTES)        // 196608
#define VA_OFF    (PRE_OFF + 4096)
#define RED_OFF   (VA_OFF + 4096)
#define SMEM_BYTES (RED_OFF + 1024)         // ~205824

// ---------- device scratch ----------
__device__ float g_pre[BB * HH];
__device__ float g_scores[BB * SS];
__device__ float g_part[32 * BB * HH];

// ---------- helpers ----------
__device__ __forceinline__ void cp16(void* dst_smem, const void* src) {
    uint32_t d;
    asm("{ .reg .u64 t; cvta.to.shared.u64 t, %1; cvt.u32.u64 %0, t; }" : "=r"(d) : "l"(dst_smem));
    asm volatile("cp.async.cg.shared.global [%0], [%1], 16;" :: "r"(d), "l"(src) : "memory");
}
#define CP_COMMIT() asm volatile("cp.async.commit_group;" ::: "memory")
template <int N> __device__ __forceinline__ void cp_wait() {
    asm volatile("cp.async.wait_group %0;" :: "n"(N) : "memory");
}

#define MMA_TF32(c, a, b0, b1) \
    asm volatile("mma.sync.aligned.m16n8k8.row.col.f32.tf32.tf32.f32 " \
        "{%0,%1,%2,%3}, {%4,%5,%6,%7}, {%8,%9}, {%0,%1,%2,%3};" \
        : "+f"((c)[0]), "+f"((c)[1]), "+f"((c)[2]), "+f"((c)[3]) \
        : "r"((a)[0]), "r"((a)[1]), "r"((a)[2]), "r"((a)[3]), "r"(b0), "r"(b1))

__device__ __forceinline__ float ftanh(float x) {
    // tanh(x) = 1 - 2/(exp(2x)+1); MUFU-based, saturates correctly
    float e = __expf(2.0f * x);
    return 1.0f - __fdividef(2.0f, e + 1.0f);
}

// ---------------------------------------------------------------------------
// K1: pre[b,k] = query[b]·Wa_w[k] + Wa_b[k] + Ua_b[k]
// ---------------------------------------------------------------------------
__global__ void qproj_kernel(const float* __restrict__ query,
                             const float* __restrict__ Wa_w,
                             const float* __restrict__ Wa_b,
                             const float* __restrict__ Ua_b) {
    int gw = blockIdx.x * 8 + (threadIdx.x >> 5);
    int lane = threadIdx.x & 31;
    int b = gw >> 10;
    int k = gw & (HH - 1);
    const float* q = query + b * HH;
    const float* w = Wa_w + (size_t)k * HH;
    float sum = 0.f;
#pragma unroll 8
    for (int h = lane; h < HH; h += 32) sum += q[h] * w[h];
#pragma unroll
    for (int off = 16; off; off >>= 1) sum += __shfl_xor_sync(0xffffffffu, sum, off);
    if (lane == 0) g_pre[b * HH + k] = sum + Wa_b[k] + Ua_b[k];
}

// ---------------------------------------------------------------------------
// K2: fused scores via mma.sync tf32. CTA = 128(M) x 256(N) per pass,
// 4 passes, K streamed in 32-float chunks through a flat 4-stage ring that
// never drains across pass boundaries.
// grid = (S/128, B), block = 256 (8 warps: 4 in M x 2 in N; warp tile 32x128).
// ---------------------------------------------------------------------------
__global__ __launch_bounds__(256, 1) void scores_kernel(
    const float* __restrict__ keys,
    const float* __restrict__ Ua_w,
    const float* __restrict__ Va_w) {
    extern __shared__ char smem[];
    float* pre_s = (float*)(smem + PRE_OFF);
    float* va_s  = (float*)(smem + VA_OFF);
    float* red   = (float*)(smem + RED_OFF);   // [2][128]

    const int tid = threadIdx.x;
    const int wid = tid >> 5;
    const int lane = tid & 31;
    const int g = lane >> 2;       // group 0..7
    const int tg = lane & 3;       // thread-in-group
    const int wm = wid & 3;        // warp M index 0..3
    const int wn = wid >> 2;       // warp N index 0..1
    const int b = blockIdx.y;
    const int s0 = blockIdx.x * MT;

    const char* gA = (const char*)(keys + ((size_t)b * SS + s0) * HH);

#pragma unroll
    for (int i = tid; i < HH; i += 256) {
        pre_s[i] = g_pre[b * HH + i];
        va_s[i]  = Va_w[i];
    }

    // chunk loader: flat chunk index cl -> stage cl&3, kc = cl&31, nt = cl>>5
    auto load_chunk = [&](int cl) {
        int st = cl & 3;
        size_t kbyte = (size_t)(cl & 31) * 128;
        char* Ab = smem + A_OFF(st);
        char* Bb = smem + B_OFF(st);
        const char* gBp = (const char*)Ua_w + ((size_t)(cl >> 5) * NTILE) * HH * 4;
#pragma unroll
        for (int r = 0; r < 4; r++) {
            int id = tid + 256 * r;
            int m = id >> 3, j = id & 7;
            uint32_t sw = (uint32_t)(j * 16) ^ ((uint32_t)(m & 7) << 4);
            cp16(Ab + m * 128 + sw, gA + (size_t)m * HH * 4 + kbyte + j * 16);
        }
#pragma unroll
        for (int r = 0; r < 8; r++) {
            int id = tid + 256 * r;
            int m = id >> 3, j = id & 7;
            uint32_t sw = (uint32_t)(j * 16) ^ ((uint32_t)(m & 7) << 4);
            cp16(Bb + m * 128 + sw, gBp + (size_t)m * HH * 4 + kbyte + j * 16);
        }
    };

    float sacc[2][2] = {{0.f, 0.f}, {0.f, 0.f}};
    float acc[2][16][4];
#pragma unroll
    for (int mi = 0; mi < 2; mi++)
#pragma unroll
        for (int ni = 0; ni < 16; ni++)
#pragma unroll
            for (int q = 0; q < 4; q++) acc[mi][ni][q] = 0.f;

    load_chunk(0); CP_COMMIT();
    load_chunk(1); CP_COMMIT();
    load_chunk(2); CP_COMMIT();

    for (int cc = 0; cc < NCHUNKS; cc++) {
        cp_wait<2>();          // chunk cc complete in this thread
        __syncthreads();       // all threads' chunk-cc data visible; stage
                               // (cc+3)&3 == (cc-1)&3 free for overwrite
        if (cc + 3 < NCHUNKS) load_chunk(cc + 3);
        CP_COMMIT();           // uniform group accounting (may be empty)

        const char* Ab = smem + A_OFF(cc & 3);
        const char* Bb = smem + B_OFF(cc & 3);
#pragma unroll
        for (int s = 0; s < 4; s++) {
            uint32_t sw  = ((uint32_t)((s * 8 + tg) * 4)) ^ ((uint32_t)g << 4);
            uint32_t sw4 = sw ^ 16u;
            uint32_t a[2][4];
#pragma unroll
            for (int mi = 0; mi < 2; mi++) {
                const char* base = Ab + (wm * 32 + mi * 16 + g) * 128;
                a[mi][0] = *(const uint32_t*)(base + sw);
                a[mi][1] = *(const uint32_t*)(base + 8 * 128 + sw);
                a[mi][2] = *(const uint32_t*)(base + sw4);
                a[mi][3] = *(const uint32_t*)(base + 8 * 128 + sw4);
            }
#pragma unroll
            for (int ni = 0; ni < 16; ni++) {
                const char* base = Bb + (wn * 128 + ni * 8 + g) * 128;
                uint32_t b0 = *(const uint32_t*)(base + sw);
                uint32_t b1 = *(const uint32_t*)(base + sw4);
                MMA_TF32(acc[0][ni], a[0], b0, b1);
                MMA_TF32(acc[1][ni], a[1], b0, b1);
            }
        }

        if ((cc & 31) == 31) {
            // end of an n-pass: tanh + Va reduce (registers + smem consts only)
            int nt = cc >> 5;
#pragma unroll
            for (int mi = 0; mi < 2; mi++) {
#pragma unroll
                for (int ni = 0; ni < 16; ni++) {
                    int col0 = nt * NTILE + wn * 128 + ni * 8 + tg * 2;
                    float p0 = pre_s[col0], p1 = pre_s[col0 + 1];
                    float v0 = va_s[col0],  v1 = va_s[col0 + 1];
                    sacc[mi][0] += ftanh(acc[mi][ni][0] + p0) * v0
                                 + ftanh(acc[mi][ni][1] + p1) * v1;
                    sacc[mi][1] += ftanh(acc[mi][ni][2] + p0) * v0
                                 + ftanh(acc[mi][ni][3] + p1) * v1;
                    acc[mi][ni][0] = 0.f; acc[mi][ni][1] = 0.f;
                    acc[mi][ni][2] = 0.f; acc[mi][ni][3] = 0.f;
                }
            }
        }
    }

    // quad reduce, then across the two N-warps via smem
#pragma unroll
    for (int mi = 0; mi < 2; mi++)
#pragma unroll
        for (int h = 0; h < 2; h++) {
            float v = sacc[mi][h];
            v += __shfl_xor_sync(0xffffffffu, v, 1);
            v += __shfl_xor_sync(0xffffffffu, v, 2);
            if (tg == 0) red[wn * 128 + wm * 32 + mi * 16 + h * 8 + g] = v;
        }
    __syncthreads();
    if (tid < 128)
        g_scores[b * SS + s0 + tid] = red[tid] + red[128 + tid];
}

// ---------------------------------------------------------------------------
// K3: softmax over S per batch (Va_b dropped: shift-invariant).
// ---------------------------------------------------------------------------
__global__ void softmax_kernel(float* __restrict__ out_w) {
    int b = blockIdx.x;
    int tid = threadIdx.x;
    __shared__ float red[256];
    float v[8];
    float mx = -1e30f;
#pragma unroll
    for (int j = 0; j < 8; j++) {
        v[j] = g_scores[b * SS + tid + 256 * j];
        mx = fmaxf(mx, v[j]);
    }
    red[tid] = mx;
    __syncthreads();
    for (int off = 128; off; off >>= 1) {
        if (tid < off) red[tid] = fmaxf(red[tid], red[tid + off]);
        __syncthreads();
    }
    mx = red[0];
    __syncthreads();
    float sum = 0.f;
#pragma unroll
    for (int j = 0; j < 8; j++) {
        v[j] = __expf(v[j] - mx);
        sum += v[j];
    }
    red[tid] = sum;
    __syncthreads();
    for (int off = 128; off; off >>= 1) {
        if (tid < off) red[tid] += red[tid + off];
        __syncthreads();
    }
    float inv = 1.f / red[0];
#pragma unroll
    for (int j = 0; j < 8; j++) out_w[b * SS + tid + 256 * j] = v[j] * inv;
}

// ---------------------------------------------------------------------------
// K4a: context partials over 32 S-chunks of 64 (deterministic, no atomics)
// ---------------------------------------------------------------------------
__global__ void context_part_kernel(const float* __restrict__ keys,
                                    const float* __restrict__ w) {
    int b = blockIdx.x;
    int cy = blockIdx.y;
    int s0 = cy * 64;
    int t = threadIdx.x;
    __shared__ float ws[64];
    if (t < 64) ws[t] = w[b * SS + s0 + t];
    __syncthreads();
    const float4* kb = (const float4*)(keys + ((size_t)b * SS + s0) * HH);
    float4 acc = {0.f, 0.f, 0.f, 0.f};
    for (int s = 0; s < 64; s += 4) {
#pragma unroll
        for (int u = 0; u < 4; u++) {
            float wv = ws[s + u];
            float4 kv = kb[(size_t)(s + u) * (HH / 4) + t];
            acc.x += wv * kv.x; acc.y += wv * kv.y;
            acc.z += wv * kv.z; acc.w += wv * kv.w;
        }
    }
    *(float4*)&g_part[((size_t)cy * BB + b) * HH + t * 4] = acc;
}

__global__ void context_reduce_kernel(float* __restrict__ ctx) {
    int i = blockIdx.x * 256 + threadIdx.x;
    float s = 0.f;
#pragma unroll
    for (int j = 0; j < 32; j++) s += g_part[(size_t)j * BB * HH + i];
    ctx[i] = s;
}

// ---------------------------------------------------------------------------
extern "C" void kernel_launch(void* const* d_in, const int* in_sizes, int n_in,
                              void* d_out, int out_size) {
    const float* query = (const float*)d_in[0];
    const float* keys  = (const float*)d_in[1];
    const float* Wa_w  = (const float*)d_in[2];
    const float* Wa_b  = (const float*)d_in[3];
    const float* Ua_w  = (const float*)d_in[4];
    const float* Ua_b  = (const float*)d_in[5];
    const float* Va_w  = (const float*)d_in[6];
    // d_in[7] = Va_b: softmax shift-invariant, unused.

    float* out = (float*)d_out;
    float* out_ctx = out;            // [B,1,H]
    float* out_w = out + BB * HH;    // [B,1,S]

    cudaFuncSetAttribute(scores_kernel, cudaFuncAttributeMaxDynamicSharedMemorySize,
                         SMEM_BYTES);

    qproj_kernel<<<BB * HH / 8, 256>>>(query, Wa_w, Wa_b, Ua_b);
    scores_kernel<<<dim3(SS / MT, BB), 256, SMEM_BYTES>>>(keys, Ua_w, Va_w);
    softmax_kernel<<<BB, 256>>>(out_w);
    context_part_kernel<<<dim3(BB, 32), 256>>>(keys, out_w);
    context_reduce_kernel<<<BB * HH / 256, 256>>>(out_ctx);
}

// round 10
// speedup vs baseline: 7.2696x; 1.6745x over previous
#include <cuda_runtime.h>
#include <cuda_bf16.h>
#include <cuda_fp16.h>
#include <cstdint>

#define BB 32
#define SS 2048
#define HH 1024

// scores kernel geometry (fp16 operands)
#define MT 128              // CTA M (keys rows)
#define NTILE 256           // CTA N per pass
#define NPASS (HH / NTILE)  // 4
#define KC 64               // K halves per chunk (128B per row)
#define CPP (HH / KC)       // chunks per pass = 16
#define NCHUNKS (NPASS * CPP)  // 64
#define NSTG 4

#define STG_BYTES (16384 + 32768)   // A 16KB + B 32KB
#define A_OFF(s)  ((s) * STG_BYTES)
#define B_OFF(s)  ((s) * STG_BYTES + 16384)
#define PRE_OFF   (NSTG * STG_BYTES)
#define VA_OFF    (PRE_OFF + 4096)
#define RED_OFF   (VA_OFF + 4096)
#define SMEM_BYTES (RED_OFF + 1024)

// ---------- device scratch ----------
__device__ float g_pre[BB * HH];
__device__ float g_scores[BB * SS];
__device__ float g_part[32 * BB * HH];
__device__ __align__(16) __half g_keys_h[(size_t)BB * SS * HH];  // 128 MB
__device__ __align__(16) __half g_ua_h[HH * HH];                 // 2 MB

// ---------- helpers ----------
__device__ __forceinline__ void cp16(void* dst_smem, const void* src) {
    uint32_t d;
    asm("{ .reg .u64 t; cvta.to.shared.u64 t, %1; cvt.u32.u64 %0, t; }" : "=r"(d) : "l"(dst_smem));
    asm volatile("cp.async.cg.shared.global [%0], [%1], 16;" :: "r"(d), "l"(src) : "memory");
}
#define CP_COMMIT() asm volatile("cp.async.commit_group;" ::: "memory")
template <int N> __device__ __forceinline__ void cp_wait() {
    asm volatile("cp.async.wait_group %0;" :: "n"(N) : "memory");
}
#define LDSM_X4(r0, r1, r2, r3, addr) \
    asm volatile("ldmatrix.sync.aligned.m8n8.x4.shared.b16 {%0,%1,%2,%3}, [%4];" \
        : "=r"(r0), "=r"(r1), "=r"(r2), "=r"(r3) : "r"(addr))
#define MMA_F16(c, a, b0, b1) \
    asm volatile("mma.sync.aligned.m16n8k16.row.col.f32.f16.f16.f32 " \
        "{%0,%1,%2,%3}, {%4,%5,%6,%7}, {%8,%9}, {%0,%1,%2,%3};" \
        : "+f"((c)[0]), "+f"((c)[1]), "+f"((c)[2]), "+f"((c)[3]) \
        : "r"((a)[0]), "r"((a)[1]), "r"((a)[2]), "r"((a)[3]), "r"(b0), "r"(b1))

__device__ __forceinline__ float ftanh(float x) {
    float e = __expf(2.0f * x);
    return 1.0f - __fdividef(2.0f, e + 1.0f);
}

// ---------------------------------------------------------------------------
// K0: f32 -> fp16 conversion (8 floats / thread, vectorized)
// ---------------------------------------------------------------------------
__global__ void cvt_kernel(const float4* __restrict__ src, __half2* __restrict__ dst) {
    size_t i = (size_t)blockIdx.x * blockDim.x + threadIdx.x;
    float4 a = src[2 * i];
    float4 b = src[2 * i + 1];
    dst[4 * i + 0] = __floats2half2_rn(a.x, a.y);
    dst[4 * i + 1] = __floats2half2_rn(a.z, a.w);
    dst[4 * i + 2] = __floats2half2_rn(b.x, b.y);
    dst[4 * i + 3] = __floats2half2_rn(b.z, b.w);
}

// ---------------------------------------------------------------------------
// K1: pre[b,k] = query[b]·Wa_w[k] + Wa_b[k] + Ua_b[k]  (fp32, accuracy anchor)
// ---------------------------------------------------------------------------
__global__ void qproj_kernel(const float* __restrict__ query,
                             const float* __restrict__ Wa_w,
                             const float* __restrict__ Wa_b,
                             const float* __restrict__ Ua_b) {
    int gw = blockIdx.x * 8 + (threadIdx.x >> 5);
    int lane = threadIdx.x & 31;
    int b = gw >> 10;
    int k = gw & (HH - 1);
    const float* q = query + b * HH;
    const float* w = Wa_w + (size_t)k * HH;
    float sum = 0.f;
#pragma unroll 8
    for (int h = lane; h < HH; h += 32) sum += q[h] * w[h];
#pragma unroll
    for (int off = 16; off; off >>= 1) sum += __shfl_xor_sync(0xffffffffu, sum, off);
    if (lane == 0) g_pre[b * HH + k] = sum + Wa_b[k] + Ua_b[k];
}

// ---------------------------------------------------------------------------
// K2: fused scores via mma.sync m16n8k16 fp16 (fp32 accum).
// CTA 128(M) x 256(N) per pass, 4 passes; K streamed in 64-half chunks
// through a flat 4-stage cp.async ring; ldmatrix.x4 fragment loads.
// grid = (S/128, B), block = 256 (8 warps: 4 M x 2 N; warp tile 32x128).
// ---------------------------------------------------------------------------
__global__ __launch_bounds__(256, 1) void scores_kernel(const float* __restrict__ Va_w) {
    extern __shared__ char smem[];
    float* pre_s = (float*)(smem + PRE_OFF);
    float* va_s  = (float*)(smem + VA_OFF);
    float* red   = (float*)(smem + RED_OFF);

    const int tid = threadIdx.x;
    const int wid = tid >> 5;
    const int lane = tid & 31;
    const int g = lane >> 2;
    const int tg = lane & 3;
    const int wm = wid & 3;
    const int wn = wid >> 2;
    const int b = blockIdx.y;
    const int s0 = blockIdx.x * MT;

    uint32_t sb32;
    asm("{ .reg .u64 t; cvta.to.shared.u64 t, %1; cvt.u32.u64 %0, t; }"
        : "=r"(sb32) : "l"(smem));

    const char* gA = (const char*)(g_keys_h + ((size_t)b * SS + s0) * HH);

#pragma unroll
    for (int i = tid; i < HH; i += 256) {
        pre_s[i] = g_pre[b * HH + i];
        va_s[i]  = Va_w[i];
    }

    // per-thread ldmatrix lane invariants (swizzle term reduces to (lane&7)<<4)
    const uint32_t xr = (uint32_t)(lane & 7) << 4;
    const int a_row   = wm * 32 + ((lane >> 3) & 1) * 8 + (lane & 7);  // + mi*16
    const uint32_t a_koff = (uint32_t)(lane >> 4) * 16;
    const int b_nrow  = wn * 128 + ((lane >> 4) << 3) + (lane & 7);    // + np*16
    const uint32_t b_koff = (uint32_t)((lane >> 3) & 1) * 16;

    // chunk loader: flat chunk cl -> stage cl&3, kbyte=(cl%CPP)*128, nt=cl/CPP
    auto load_chunk = [&](int cl) {
        int st = cl & 3;
        size_t kbyte = (size_t)(cl & (CPP - 1)) * 128;
        char* Ab = smem + A_OFF(st);
        char* Bb = smem + B_OFF(st);
        const char* gBp = (const char*)(g_ua_h + ((size_t)(cl >> 4) * NTILE) * HH);
#pragma unroll
        for (int r = 0; r < 4; r++) {
            int id = tid + 256 * r;
            int m = id >> 3, j = id & 7;
            uint32_t sw = (uint32_t)(j * 16) ^ ((uint32_t)(m & 7) << 4);
            cp16(Ab + m * 128 + sw, gA + (size_t)m * (HH * 2) + kbyte + j * 16);
        }
#pragma unroll
        for (int r = 0; r < 8; r++) {
            int id = tid + 256 * r;
            int m = id >> 3, j = id & 7;
            uint32_t sw = (uint32_t)(j * 16) ^ ((uint32_t)(m & 7) << 4);
            cp16(Bb + m * 128 + sw, gBp + (size_t)m * (HH * 2) + kbyte + j * 16);
        }
    };

    float sacc[2][2] = {{0.f, 0.f}, {0.f, 0.f}};
    float acc[2][16][4];
#pragma unroll
    for (int mi = 0; mi < 2; mi++)
#pragma unroll
        for (int ni = 0; ni < 16; ni++)
#pragma unroll
            for (int q = 0; q < 4; q++) acc[mi][ni][q] = 0.f;

    load_chunk(0); CP_COMMIT();
    load_chunk(1); CP_COMMIT();
    load_chunk(2); CP_COMMIT();

    for (int cc = 0; cc < NCHUNKS; cc++) {
        cp_wait<2>();
        __syncthreads();                       // chunk cc visible; stage (cc-1)&3 free
        if (cc + 3 < NCHUNKS) load_chunk(cc + 3);
        CP_COMMIT();                           // uniform group accounting

        uint32_t Ab32 = sb32 + A_OFF(cc & 3);
        uint32_t Bb32 = sb32 + B_OFF(cc & 3);
#pragma unroll
        for (int s = 0; s < 4; s++) {          // 4 k-steps of 16 halves
            uint32_t a[2][4];
#pragma unroll
            for (int mi = 0; mi < 2; mi++) {
                uint32_t addr = Ab32 + (uint32_t)(a_row + mi * 16) * 128
                              + (((uint32_t)s * 32 + a_koff) ^ xr);
                LDSM_X4(a[mi][0], a[mi][1], a[mi][2], a[mi][3], addr);
            }
#pragma unroll
            for (int np = 0; np < 8; np++) {   // pairs of n-tiles (16 n each)
                uint32_t bf[4];
                uint32_t addr = Bb32 + (uint32_t)(b_nrow + np * 16) * 128
                              + (((uint32_t)s * 32 + b_koff) ^ xr);
                LDSM_X4(bf[0], bf[1], bf[2], bf[3], addr);
                MMA_F16(acc[0][np * 2],     a[0], bf[0], bf[1]);
                MMA_F16(acc[1][np * 2],     a[1], bf[0], bf[1]);
                MMA_F16(acc[0][np * 2 + 1], a[0], bf[2], bf[3]);
                MMA_F16(acc[1][np * 2 + 1], a[1], bf[2], bf[3]);
            }
        }

        if ((cc & (CPP - 1)) == CPP - 1) {
            // end of an n-pass: tanh + Va reduce, reset accumulators
            int nt = cc >> 4;
#pragma unroll
            for (int mi = 0; mi < 2; mi++) {
#pragma unroll
                for (int ni = 0; ni < 16; ni++) {
                    int col0 = nt * NTILE + wn * 128 + ni * 8 + tg * 2;
                    float p0 = pre_s[col0], p1 = pre_s[col0 + 1];
                    float v0 = va_s[col0],  v1 = va_s[col0 + 1];
                    sacc[mi][0] += ftanh(acc[mi][ni][0] + p0) * v0
                                 + ftanh(acc[mi][ni][1] + p1) * v1;
                    sacc[mi][1] += ftanh(acc[mi][ni][2] + p0) * v0
                                 + ftanh(acc[mi][ni][3] + p1) * v1;
                    acc[mi][ni][0] = 0.f; acc[mi][ni][1] = 0.f;
                    acc[mi][ni][2] = 0.f; acc[mi][ni][3] = 0.f;
                }
            }
        }
    }

    // quad reduce (lanes sharing rows), then across the two N-warps via smem
#pragma unroll
    for (int mi = 0; mi < 2; mi++)
#pragma unroll
        for (int h = 0; h < 2; h++) {
            float v = sacc[mi][h];
            v += __shfl_xor_sync(0xffffffffu, v, 1);
            v += __shfl_xor_sync(0xffffffffu, v, 2);
            if (tg == 0) red[wn * 128 + wm * 32 + mi * 16 + h * 8 + g] = v;
        }
    __syncthreads();
    if (tid < 128)
        g_scores[b * SS + s0 + tid] = red[tid] + red[128 + tid];
}

// ---------------------------------------------------------------------------
// K3: softmax over S per batch (Va_b dropped: shift-invariant).
// ---------------------------------------------------------------------------
__global__ void softmax_kernel(float* __restrict__ out_w) {
    int b = blockIdx.x;
    int tid = threadIdx.x;
    __shared__ float red[256];
    float v[8];
    float mx = -1e30f;
#pragma unroll
    for (int j = 0; j < 8; j++) {
        v[j] = g_scores[b * SS + tid + 256 * j];
        mx = fmaxf(mx, v[j]);
    }
    red[tid] = mx;
    __syncthreads();
    for (int off = 128; off; off >>= 1) {
        if (tid < off) red[tid] = fmaxf(red[tid], red[tid + off]);
        __syncthreads();
    }
    mx = red[0];
    __syncthreads();
    float sum = 0.f;
#pragma unroll
    for (int j = 0; j < 8; j++) {
        v[j] = __expf(v[j] - mx);
        sum += v[j];
    }
    red[tid] = sum;
    __syncthreads();
    for (int off = 128; off; off >>= 1) {
        if (tid < off) red[tid] += red[tid + off];
        __syncthreads();
    }
    float inv = 1.f / red[0];
#pragma unroll
    for (int j = 0; j < 8; j++) out_w[b * SS + tid + 256 * j] = v[j] * inv;
}

// ---------------------------------------------------------------------------
// K4a: context partials over 32 S-chunks of 64 (deterministic, f32 keys)
// ---------------------------------------------------------------------------
__global__ void context_part_kernel(const float* __restrict__ keys,
                                    const float* __restrict__ w) {
    int b = blockIdx.x;
    int cy = blockIdx.y;
    int s0 = cy * 64;
    int t = threadIdx.x;
    __shared__ float ws[64];
    if (t < 64) ws[t] = w[b * SS + s0 + t];
    __syncthreads();
    const float4* kb = (const float4*)(keys + ((size_t)b * SS + s0) * HH);
    float4 acc = {0.f, 0.f, 0.f, 0.f};
    for (int s = 0; s < 64; s += 4) {
#pragma unroll
        for (int u = 0; u < 4; u++) {
            float wv = ws[s + u];
            float4 kv = kb[(size_t)(s + u) * (HH / 4) + t];
            acc.x += wv * kv.x; acc.y += wv * kv.y;
            acc.z += wv * kv.z; acc.w += wv * kv.w;
        }
    }
    *(float4*)&g_part[((size_t)cy * BB + b) * HH + t * 4] = acc;
}

__global__ void context_reduce_kernel(float* __restrict__ ctx) {
    int i = blockIdx.x * 256 + threadIdx.x;
    float s = 0.f;
#pragma unroll
    for (int j = 0; j < 32; j++) s += g_part[(size_t)j * BB * HH + i];
    ctx[i] = s;
}

// ---------------------------------------------------------------------------
extern "C" void kernel_launch(void* const* d_in, const int* in_sizes, int n_in,
                              void* d_out, int out_size) {
    const float* query = (const float*)d_in[0];
    const float* keys  = (const float*)d_in[1];
    const float* Wa_w  = (const float*)d_in[2];
    const float* Wa_b  = (const float*)d_in[3];
    const float* Ua_w  = (const float*)d_in[4];
    const float* Ua_b  = (const float*)d_in[5];
    const float* Va_w  = (const float*)d_in[6];
    // d_in[7] = Va_b: softmax shift-invariant, unused.

    float* out = (float*)d_out;
    float* out_ctx = out;            // [B,1,H]
    float* out_w = out + BB * HH;    // [B,1,S]

    __half* keys_h = nullptr;
    __half* ua_h = nullptr;
    cudaGetSymbolAddress((void**)&keys_h, g_keys_h);
    cudaGetSymbolAddress((void**)&ua_h, g_ua_h);

    cudaFuncSetAttribute(scores_kernel, cudaFuncAttributeMaxDynamicSharedMemorySize,
                         SMEM_BYTES);

    // fp16 conversions (8 floats/thread)
    cvt_kernel<<<((size_t)BB * SS * HH / 8) / 256, 256>>>(
        (const float4*)keys, (__half2*)keys_h);
    cvt_kernel<<<(HH * HH / 8) / 256, 256>>>(
        (const float4*)Ua_w, (__half2*)ua_h);

    qproj_kernel<<<BB * HH / 8, 256>>>(query, Wa_w, Wa_b, Ua_b);
    scores_kernel<<<dim3(SS / MT, BB), 256, SMEM_BYTES>>>(Va_w);
    softmax_kernel<<<BB, 256>>>(out_w);
    context_part_kernel<<<dim3(BB, 32), 256>>>(keys, out_w);
    context_reduce_kernel<<<BB * HH / 256, 256>>>(out_ctx);
}